// round 1
// baseline (speedup 1.0000x reference)
#include <cuda_runtime.h>
#include <cuda_bf16.h>

#define N_NODES 100000
#define N_EDGES 3200000
#define IN_F    256
#define OUT_F   64

// ---------------------------------------------------------------------------
// Scratch (no allocations allowed -> __device__ globals)
// ---------------------------------------------------------------------------
__device__ int   g_deg[N_NODES];
__device__ float g_norm[N_NODES];
__device__ float g_feat[N_NODES * OUT_F];   // pre-multiplied features (gather side)
__device__ float g_acc [N_NODES * OUT_F];   // scatter-add accumulator

// ---------------------------------------------------------------------------
// Zero accumulator + degree (must happen every call: graph replays)
// ---------------------------------------------------------------------------
__global__ void k_zero() {
    int i = blockIdx.x * blockDim.x + threadIdx.x;      // 0 .. 6.4M-1
    if (i < N_NODES * OUT_F) g_acc[i] = 0.0f;
    if (i < N_NODES)         g_deg[i] = 0;
}

// ---------------------------------------------------------------------------
// In-degree via int atomics
// ---------------------------------------------------------------------------
__global__ void k_deg(const int* __restrict__ dst) {
    int e = blockIdx.x * blockDim.x + threadIdx.x;
    if (e < N_EDGES) atomicAdd(&g_deg[dst[e]], 1);
}

__global__ void k_norm() {
    int i = blockIdx.x * blockDim.x + threadIdx.x;
    if (i < N_NODES) {
        float d = (float)g_deg[i];
        g_norm[i] = rsqrtf(d < 1.0f ? 1.0f : d);
    }
}

// ---------------------------------------------------------------------------
// GEMM: g_feat[n][c] = (x[n,:] . W[:,c]) * norm[n]
// Block = 256 threads, 16 nodes/block, K tiled in 2 chunks of 128 (48KB smem).
// thread t: node = t>>4, columns [4*(t&15), 4*(t&15)+3]
// ---------------------------------------------------------------------------
#define NODES_PER_BLK 16
#define K_CHUNK       128

__global__ __launch_bounds__(256) void k_gemm(const float* __restrict__ x,
                                              const float* __restrict__ W) {
    __shared__ float sW[K_CHUNK * OUT_F];          // 32 KB
    __shared__ float sx[NODES_PER_BLK * K_CHUNK];  // 8 KB

    const int t     = threadIdx.x;
    const int node0 = blockIdx.x * NODES_PER_BLK;  // 6250 blocks * 16 = 100000 exact
    const int node  = t >> 4;
    const int cg    = (t & 15) * 4;

    float4 acc = make_float4(0.f, 0.f, 0.f, 0.f);

    for (int kc = 0; kc < IN_F; kc += K_CHUNK) {
        __syncthreads();
        // load W chunk: 128*64 floats = 2048 float4 -> 8 per thread
        const float4* W4  = (const float4*)(W + (size_t)kc * OUT_F);
        float4*       sW4 = (float4*)sW;
        #pragma unroll
        for (int i = 0; i < 8; i++) sW4[t + 256 * i] = W4[t + 256 * i];
        // load x chunk: 16 rows x 128 = 512 float4 -> 2 per thread
        float4* sx4 = (float4*)sx;
        #pragma unroll
        for (int i = 0; i < 2; i++) {
            int idx = t + 256 * i;           // 0..511
            int r   = idx / (K_CHUNK / 4);   // row 0..15
            int c   = idx % (K_CHUNK / 4);   // float4 col 0..31
            sx4[idx] = ((const float4*)(x + (size_t)(node0 + r) * IN_F + kc))[c];
        }
        __syncthreads();

        const float* xr = sx + node * K_CHUNK;
        #pragma unroll 8
        for (int k = 0; k < K_CHUNK; k++) {
            float  xv = xr[k];
            float4 w  = *(const float4*)(sW + k * OUT_F + cg);
            acc.x = fmaf(xv, w.x, acc.x);
            acc.y = fmaf(xv, w.y, acc.y);
            acc.z = fmaf(xv, w.z, acc.z);
            acc.w = fmaf(xv, w.w, acc.w);
        }
    }

    float nm = g_norm[node0 + node];
    acc.x *= nm; acc.y *= nm; acc.z *= nm; acc.w *= nm;
    *(float4*)(g_feat + (size_t)(node0 + node) * OUT_F + cg) = acc;
}

// ---------------------------------------------------------------------------
// Edge scatter: g_acc[dst] += g_feat[src], one float4 per thread
// (16 threads per edge -> coalesced 256B row read + vector red.global.add.v4)
// ---------------------------------------------------------------------------
__global__ __launch_bounds__(256) void k_scatter(const int* __restrict__ src,
                                                 const int* __restrict__ dst) {
    long long idx = (long long)blockIdx.x * blockDim.x + threadIdx.x;
    if (idx >= (long long)N_EDGES * 16) return;
    int e = (int)(idx >> 4);
    int v = ((int)idx & 15) << 2;
    int s = src[e];
    int d = dst[e];
    float4 val = *(const float4*)(g_feat + (size_t)s * OUT_F + v);
    float* p = g_acc + (size_t)d * OUT_F + v;
    asm volatile("red.global.add.v4.f32 [%0], {%1, %2, %3, %4};"
                 :: "l"(p), "f"(val.x), "f"(val.y), "f"(val.z), "f"(val.w)
                 : "memory");
}

// ---------------------------------------------------------------------------
// Between steps: feat = acc * norm^2 (post-norm of step1 + pre-norm of step2),
// and re-zero acc for the next scatter. One float4 per thread.
// ---------------------------------------------------------------------------
__global__ void k_mid() {
    int i = blockIdx.x * blockDim.x + threadIdx.x;   // over N*64/4 float4s
    if (i >= N_NODES * OUT_F / 4) return;
    int node = i >> 4;
    float nm = g_norm[node];
    float n2 = nm * nm;
    float4 val = ((const float4*)g_acc)[i];
    val.x *= n2; val.y *= n2; val.z *= n2; val.w *= n2;
    ((float4*)g_feat)[i] = val;
    ((float4*)g_acc)[i]  = make_float4(0.f, 0.f, 0.f, 0.f);
}

// ---------------------------------------------------------------------------
// Epilogue: out = acc * norm + b
// ---------------------------------------------------------------------------
__global__ void k_out(float* __restrict__ out, const float* __restrict__ b) {
    int i = blockIdx.x * blockDim.x + threadIdx.x;   // over N*64/4 float4s
    if (i >= N_NODES * OUT_F / 4) return;
    int node = i >> 4;
    int col  = (i & 15) << 2;
    float nm = g_norm[node];
    float4 bb  = *(const float4*)(b + col);
    float4 val = ((const float4*)g_acc)[i];
    val.x = fmaf(val.x, nm, bb.x);
    val.y = fmaf(val.y, nm, bb.y);
    val.z = fmaf(val.z, nm, bb.z);
    val.w = fmaf(val.w, nm, bb.w);
    ((float4*)out)[i] = val;
}

// ---------------------------------------------------------------------------
// Launch: inputs are x, src, dst, W, b (metadata order)
// ---------------------------------------------------------------------------
extern "C" void kernel_launch(void* const* d_in, const int* in_sizes, int n_in,
                              void* d_out, int out_size) {
    const float* x   = (const float*)d_in[0];
    const int*   src = (const int*)  d_in[1];
    const int*   dst = (const int*)  d_in[2];
    const float* W   = (const float*)d_in[3];
    const float* b   = (const float*)d_in[4];
    float*       out = (float*)d_out;

    const int nf   = N_NODES * OUT_F;          // 6.4M
    const int nf4  = nf / 4;                   // 1.6M float4s
    const long long escat = (long long)N_EDGES * 16;

    k_zero<<<(nf + 255) / 256, 256>>>();
    k_deg <<<(N_EDGES + 255) / 256, 256>>>(dst);
    k_norm<<<(N_NODES + 255) / 256, 256>>>();
    k_gemm<<<N_NODES / NODES_PER_BLK, 256>>>(x, W);

    // Step 1
    k_scatter<<<(unsigned)((escat + 255) / 256), 256>>>(src, dst);
    k_mid<<<(nf4 + 255) / 256, 256>>>();

    // Step 2
    k_scatter<<<(unsigned)((escat + 255) / 256), 256>>>(src, dst);
    k_out<<<(nf4 + 255) / 256, 256>>>(out, b);
}

// round 3
// speedup vs baseline: 1.4222x; 1.4222x over previous
#include <cuda_runtime.h>
#include <cuda_bf16.h>

#define N_NODES 100000
#define N_EDGES 3200000
#define IN_F    256
#define OUT_F   64

// ---------------------------------------------------------------------------
// Scratch (no allocations allowed -> __device__ globals).
// NOTE: never passed as kernel arguments from host (host-side symbol name is
// the shadow, not the device address) — kernels reference them directly.
// ---------------------------------------------------------------------------
__device__ int   g_deg [N_NODES];
__device__ int   g_cnt [N_NODES];
__device__ int   g_off [N_NODES + 1];
__device__ float g_norm[N_NODES];
__device__ int   g_esrc[N_EDGES];           // CSR-ordered source indices (by dst)
__device__ float g_feat [N_NODES * OUT_F];  // after GEMM (pre-norm applied)
__device__ float g_feat2[N_NODES * OUT_F];  // after step 1

// ---------------------------------------------------------------------------
// Zero per-call counters (graph replays re-run everything)
// ---------------------------------------------------------------------------
__global__ void k_zero() {
    int i = blockIdx.x * blockDim.x + threadIdx.x;
    if (i < N_NODES) { g_deg[i] = 0; g_cnt[i] = 0; }
}

__global__ void k_deg(const int* __restrict__ dst) {
    int e = blockIdx.x * blockDim.x + threadIdx.x;
    if (e < N_EDGES) atomicAdd(&g_deg[dst[e]], 1);
}

// ---------------------------------------------------------------------------
// Single-block exclusive scan of degrees -> CSR offsets; also computes norm.
// ---------------------------------------------------------------------------
__global__ __launch_bounds__(1024) void k_scan() {
    const int CH = (N_NODES + 1023) / 1024;   // 98
    int t = threadIdx.x;
    int base = t * CH;

    int s = 0;
    for (int i = 0; i < CH; i++) {
        int idx = base + i;
        if (idx < N_NODES) s += g_deg[idx];
    }

    __shared__ int sm[1024];
    sm[t] = s;
    __syncthreads();
    for (int off = 1; off < 1024; off <<= 1) {
        int v = (t >= off) ? sm[t - off] : 0;
        __syncthreads();
        sm[t] += v;
        __syncthreads();
    }
    int excl = sm[t] - s;

    for (int i = 0; i < CH; i++) {
        int idx = base + i;
        if (idx < N_NODES) {
            int d = g_deg[idx];
            g_off[idx] = excl;
            excl += d;
            float df = (float)d;
            g_norm[idx] = rsqrtf(df < 1.0f ? 1.0f : df);
        }
    }
    if (t == 0) g_off[N_NODES] = N_EDGES;
}

// ---------------------------------------------------------------------------
// CSR build: place src of each edge into its dst's segment
// ---------------------------------------------------------------------------
__global__ void k_csr(const int* __restrict__ src, const int* __restrict__ dst) {
    int e = blockIdx.x * blockDim.x + threadIdx.x;
    if (e < N_EDGES) {
        int d = dst[e];
        int pos = g_off[d] + atomicAdd(&g_cnt[d], 1);
        g_esrc[pos] = src[e];
    }
}

// ---------------------------------------------------------------------------
// GEMM: g_feat[n][c] = (x[n,:] . W[:,c]) * norm[n]
// 64x64 output tile / block, 256 threads, 4x4 micro-tile per thread, K chunk 64
// ---------------------------------------------------------------------------
#define MT 64
#define KC 64

__global__ __launch_bounds__(256) void k_gemm(const float* __restrict__ x,
                                              const float* __restrict__ W) {
    __shared__ float sx[MT * KC];        // [row][k]  16 KB
    __shared__ float sw[KC * OUT_F];     // [k][col]  16 KB

    const int t  = threadIdx.x;
    const int tx = t & 15;               // col group: cols 4*tx .. 4*tx+3
    const int ty = t >> 4;               // row group: rows 4*ty .. 4*ty+3
    const int node0 = blockIdx.x * MT;

    float4 acc0 = make_float4(0.f,0.f,0.f,0.f);
    float4 acc1 = make_float4(0.f,0.f,0.f,0.f);
    float4 acc2 = make_float4(0.f,0.f,0.f,0.f);
    float4 acc3 = make_float4(0.f,0.f,0.f,0.f);

    for (int kc = 0; kc < IN_F; kc += KC) {
        __syncthreads();
        const float4* Wg = (const float4*)(W + (size_t)kc * OUT_F);
        #pragma unroll
        for (int i = 0; i < 4; i++)
            ((float4*)sw)[t + 256 * i] = Wg[t + 256 * i];
        #pragma unroll
        for (int i = 0; i < 4; i++) {
            int idx = t + 256 * i;       // float4 index: r*16 + c4
            int r   = idx >> 4;
            int c4  = idx & 15;
            int n   = node0 + r;
            float4 v = (n < N_NODES)
                ? *(const float4*)(x + (size_t)n * IN_F + kc + 4 * c4)
                : make_float4(0.f,0.f,0.f,0.f);
            ((float4*)sx)[idx] = v;
        }
        __syncthreads();

        #pragma unroll
        for (int k = 0; k < KC; k += 4) {
            float4 a0 = *(const float4*)(sx + (4*ty+0) * KC + k);
            float4 a1 = *(const float4*)(sx + (4*ty+1) * KC + k);
            float4 a2 = *(const float4*)(sx + (4*ty+2) * KC + k);
            float4 a3 = *(const float4*)(sx + (4*ty+3) * KC + k);
            float4 b0 = *(const float4*)(sw + (k+0) * OUT_F + 4*tx);
            float4 b1 = *(const float4*)(sw + (k+1) * OUT_F + 4*tx);
            float4 b2 = *(const float4*)(sw + (k+2) * OUT_F + 4*tx);
            float4 b3 = *(const float4*)(sw + (k+3) * OUT_F + 4*tx);

            #define FMA4(A, AK, B) \
                A.x = fmaf(AK, B.x, A.x); A.y = fmaf(AK, B.y, A.y); \
                A.z = fmaf(AK, B.z, A.z); A.w = fmaf(AK, B.w, A.w);
            FMA4(acc0, a0.x, b0) FMA4(acc0, a0.y, b1) FMA4(acc0, a0.z, b2) FMA4(acc0, a0.w, b3)
            FMA4(acc1, a1.x, b0) FMA4(acc1, a1.y, b1) FMA4(acc1, a1.z, b2) FMA4(acc1, a1.w, b3)
            FMA4(acc2, a2.x, b0) FMA4(acc2, a2.y, b1) FMA4(acc2, a2.z, b2) FMA4(acc2, a2.w, b3)
            FMA4(acc3, a3.x, b0) FMA4(acc3, a3.y, b1) FMA4(acc3, a3.z, b2) FMA4(acc3, a3.w, b3)
            #undef FMA4
        }
    }

    #pragma unroll
    for (int r = 0; r < 4; r++) {
        int n = node0 + 4*ty + r;
        if (n < N_NODES) {
            float nm = g_norm[n];
            float4 a = r==0 ? acc0 : r==1 ? acc1 : r==2 ? acc2 : acc3;
            a.x *= nm; a.y *= nm; a.z *= nm; a.w *= nm;
            *(float4*)(g_feat + (size_t)n * OUT_F + 4*tx) = a;
        }
    }
}

// ---------------------------------------------------------------------------
// Warp-per-node gather core: each lane owns 2 contiguous cols (float2).
// Sums fin[esrc[e]] over the node's CSR segment.
// ---------------------------------------------------------------------------
__device__ __forceinline__ float2 gather_sum(const float* fin, int node, int lane) {
    int start = g_off[node];
    int end   = g_off[node + 1];
    const float2* f2 = (const float2*)fin;

    float ax = 0.f, ay = 0.f, bx = 0.f, by = 0.f;
    for (int j = start; j < end; j += 32) {
        int rem = end - j;
        int myidx = (lane < rem) ? g_esrc[j + lane] : 0;
        if (rem >= 32) {
            #pragma unroll 8
            for (int tt = 0; tt < 32; tt += 2) {
                int s0 = __shfl_sync(0xffffffffu, myidx, tt);
                int s1 = __shfl_sync(0xffffffffu, myidx, tt + 1);
                float2 v0 = f2[(size_t)s0 * 32 + lane];
                float2 v1 = f2[(size_t)s1 * 32 + lane];
                ax += v0.x; ay += v0.y;
                bx += v1.x; by += v1.y;
            }
        } else {
            for (int tt = 0; tt < rem; tt++) {
                int s0 = __shfl_sync(0xffffffffu, myidx, tt);
                float2 v0 = f2[(size_t)s0 * 32 + lane];
                ax += v0.x; ay += v0.y;
            }
        }
    }
    return make_float2(ax + bx, ay + by);
}

// Step 1: g_feat2[n] = norm[n]^2 * sum_{e in CSR[n]} g_feat[esrc[e]]
__global__ __launch_bounds__(256) void k_gather1() {
    int node = (blockIdx.x * 256 + threadIdx.x) >> 5;
    if (node >= N_NODES) return;
    int lane = threadIdx.x & 31;
    float2 s = gather_sum(g_feat, node, lane);
    float nm = g_norm[node];
    float f = nm * nm;
    s.x *= f; s.y *= f;
    ((float2*)g_feat2)[(size_t)node * 32 + lane] = s;
}

// Step 2: out[n] = norm[n] * sum_{e in CSR[n]} g_feat2[esrc[e]] + b
__global__ __launch_bounds__(256) void k_gather2(float* __restrict__ out,
                                                 const float* __restrict__ bias) {
    int node = (blockIdx.x * 256 + threadIdx.x) >> 5;
    if (node >= N_NODES) return;
    int lane = threadIdx.x & 31;
    float2 s = gather_sum(g_feat2, node, lane);
    float nm = g_norm[node];
    s.x = fmaf(s.x, nm, bias[2 * lane]);
    s.y = fmaf(s.y, nm, bias[2 * lane + 1]);
    ((float2*)out)[(size_t)node * 32 + lane] = s;
}

// ---------------------------------------------------------------------------
// Launch: inputs are x, src, dst, W, b (metadata order)
// ---------------------------------------------------------------------------
extern "C" void kernel_launch(void* const* d_in, const int* in_sizes, int n_in,
                              void* d_out, int out_size) {
    const float* x   = (const float*)d_in[0];
    const int*   src = (const int*)  d_in[1];
    const int*   dst = (const int*)  d_in[2];
    const float* W   = (const float*)d_in[3];
    const float* b   = (const float*)d_in[4];
    float*       out = (float*)d_out;

    k_zero<<<(N_NODES + 255) / 256, 256>>>();
    k_deg <<<(N_EDGES + 255) / 256, 256>>>(dst);
    k_scan<<<1, 1024>>>();
    k_csr <<<(N_EDGES + 255) / 256, 256>>>(src, dst);

    k_gemm<<<(N_NODES + MT - 1) / MT, 256>>>(x, W);

    int gather_blocks = (N_NODES * 32 + 255) / 256;   // warp per node
    k_gather1<<<gather_blocks, 256>>>();
    k_gather2<<<gather_blocks, 256>>>(out, b);
}

// round 4
// speedup vs baseline: 1.4224x; 1.0001x over previous
#include <cuda_runtime.h>
#include <cuda_fp16.h>
#include <cuda_bf16.h>

#define N_NODES 100000
#define N_EDGES 3200000
#define IN_F    256
#define OUT_F   64

// ---------------------------------------------------------------------------
// Scratch (no allocations allowed -> __device__ globals).
// Never passed as kernel arguments from host (host symbol is a shadow);
// kernels reference them directly.
// Feature scratch is fp16: one 128B line per node row -> half the L2 traffic
// of fp32 in the random gathers. Accumulation is fp32.
// ---------------------------------------------------------------------------
__device__ int     g_deg [N_NODES];
__device__ int     g_cnt [N_NODES];
__device__ int     g_off [N_NODES + 1];
__device__ float   g_norm[N_NODES];
__device__ int     g_esrc[N_EDGES];            // CSR-ordered source ids (by dst)
__device__ __half2 g_featH [N_NODES * 32];     // after GEMM (pre-norm applied)
__device__ __half2 g_feat2H[N_NODES * 32];     // after step 1

// ---------------------------------------------------------------------------
// Zero per-call counters (graph replays re-run everything)
// ---------------------------------------------------------------------------
__global__ void k_zero() {
    int i = blockIdx.x * blockDim.x + threadIdx.x;
    if (i < N_NODES) { g_deg[i] = 0; g_cnt[i] = 0; }
}

__global__ void k_deg(const int* __restrict__ dst) {
    int e = blockIdx.x * blockDim.x + threadIdx.x;
    if (e < N_EDGES) atomicAdd(&g_deg[dst[e]], 1);
}

// ---------------------------------------------------------------------------
// Single-block exclusive scan of degrees -> CSR offsets; also computes norm.
// ---------------------------------------------------------------------------
__global__ __launch_bounds__(1024) void k_scan() {
    const int CH = (N_NODES + 1023) / 1024;   // 98
    int t = threadIdx.x;
    int base = t * CH;

    int s = 0;
    for (int i = 0; i < CH; i++) {
        int idx = base + i;
        if (idx < N_NODES) s += g_deg[idx];
    }

    __shared__ int sm[1024];
    sm[t] = s;
    __syncthreads();
    for (int off = 1; off < 1024; off <<= 1) {
        int v = (t >= off) ? sm[t - off] : 0;
        __syncthreads();
        sm[t] += v;
        __syncthreads();
    }
    int excl = sm[t] - s;

    for (int i = 0; i < CH; i++) {
        int idx = base + i;
        if (idx < N_NODES) {
            int d = g_deg[idx];
            g_off[idx] = excl;
            excl += d;
            float df = (float)d;
            g_norm[idx] = rsqrtf(df < 1.0f ? 1.0f : df);
        }
    }
    if (t == 0) g_off[N_NODES] = N_EDGES;
}

// ---------------------------------------------------------------------------
// CSR build: place src of each edge into its dst's segment
// ---------------------------------------------------------------------------
__global__ void k_csr(const int* __restrict__ src, const int* __restrict__ dst) {
    int e = blockIdx.x * blockDim.x + threadIdx.x;
    if (e < N_EDGES) {
        int d = dst[e];
        int pos = g_off[d] + atomicAdd(&g_cnt[d], 1);
        g_esrc[pos] = src[e];
    }
}

// ---------------------------------------------------------------------------
// GEMM: g_featH[n][c] = half( (x[n,:] . W[:,c]) * norm[n] )
// 64x64 output tile / block, 256 threads, 4x4 micro-tile per thread, K chunk 64
// ---------------------------------------------------------------------------
#define MT 64
#define KC 64

__global__ __launch_bounds__(256) void k_gemm(const float* __restrict__ x,
                                              const float* __restrict__ W) {
    __shared__ float sx[MT * KC];        // [row][k]  16 KB
    __shared__ float sw[KC * OUT_F];     // [k][col]  16 KB

    const int t  = threadIdx.x;
    const int tx = t & 15;               // col group: cols 4*tx .. 4*tx+3
    const int ty = t >> 4;               // row group: rows 4*ty .. 4*ty+3
    const int node0 = blockIdx.x * MT;

    float4 acc0 = make_float4(0.f,0.f,0.f,0.f);
    float4 acc1 = make_float4(0.f,0.f,0.f,0.f);
    float4 acc2 = make_float4(0.f,0.f,0.f,0.f);
    float4 acc3 = make_float4(0.f,0.f,0.f,0.f);

    for (int kc = 0; kc < IN_F; kc += KC) {
        __syncthreads();
        const float4* Wg = (const float4*)(W + (size_t)kc * OUT_F);
        #pragma unroll
        for (int i = 0; i < 4; i++)
            ((float4*)sw)[t + 256 * i] = Wg[t + 256 * i];
        #pragma unroll
        for (int i = 0; i < 4; i++) {
            int idx = t + 256 * i;       // float4 index: r*16 + c4
            int r   = idx >> 4;
            int c4  = idx & 15;
            int n   = node0 + r;
            float4 v = (n < N_NODES)
                ? *(const float4*)(x + (size_t)n * IN_F + kc + 4 * c4)
                : make_float4(0.f,0.f,0.f,0.f);
            ((float4*)sx)[idx] = v;
        }
        __syncthreads();

        #pragma unroll
        for (int k = 0; k < KC; k += 4) {
            float4 a0 = *(const float4*)(sx + (4*ty+0) * KC + k);
            float4 a1 = *(const float4*)(sx + (4*ty+1) * KC + k);
            float4 a2 = *(const float4*)(sx + (4*ty+2) * KC + k);
            float4 a3 = *(const float4*)(sx + (4*ty+3) * KC + k);
            float4 b0 = *(const float4*)(sw + (k+0) * OUT_F + 4*tx);
            float4 b1 = *(const float4*)(sw + (k+1) * OUT_F + 4*tx);
            float4 b2 = *(const float4*)(sw + (k+2) * OUT_F + 4*tx);
            float4 b3 = *(const float4*)(sw + (k+3) * OUT_F + 4*tx);

            #define FMA4(A, AK, B) \
                A.x = fmaf(AK, B.x, A.x); A.y = fmaf(AK, B.y, A.y); \
                A.z = fmaf(AK, B.z, A.z); A.w = fmaf(AK, B.w, A.w);
            FMA4(acc0, a0.x, b0) FMA4(acc0, a0.y, b1) FMA4(acc0, a0.z, b2) FMA4(acc0, a0.w, b3)
            FMA4(acc1, a1.x, b0) FMA4(acc1, a1.y, b1) FMA4(acc1, a1.z, b2) FMA4(acc1, a1.w, b3)
            FMA4(acc2, a2.x, b0) FMA4(acc2, a2.y, b1) FMA4(acc2, a2.z, b2) FMA4(acc2, a2.w, b3)
            FMA4(acc3, a3.x, b0) FMA4(acc3, a3.y, b1) FMA4(acc3, a3.z, b2) FMA4(acc3, a3.w, b3)
            #undef FMA4
        }
    }

    #pragma unroll
    for (int r = 0; r < 4; r++) {
        int n = node0 + 4*ty + r;
        if (n < N_NODES) {
            float nm = g_norm[n];
            float4 a = r==0 ? acc0 : r==1 ? acc1 : r==2 ? acc2 : acc3;
            // cols 4*tx .. 4*tx+3 -> half2 slots node*32 + 2*tx, +1
            g_featH[(size_t)n * 32 + 2*tx    ] = __floats2half2_rn(a.x * nm, a.y * nm);
            g_featH[(size_t)n * 32 + 2*tx + 1] = __floats2half2_rn(a.z * nm, a.w * nm);
        }
    }
}

// ---------------------------------------------------------------------------
// Warp-per-node gather core: each lane owns 2 contiguous cols (one half2).
// Per edge the warp reads one 128B row. Accumulation in fp32.
// ---------------------------------------------------------------------------
__device__ __forceinline__ float2 gather_sum(const __half2* __restrict__ fin,
                                             int node, int lane) {
    int start = g_off[node];
    int end   = g_off[node + 1];

    float ax = 0.f, ay = 0.f, bx = 0.f, by = 0.f;
    for (int j = start; j < end; j += 32) {
        int rem = end - j;
        int myidx = (lane < rem) ? g_esrc[j + lane] : 0;
        if (rem >= 32) {
            #pragma unroll 8
            for (int tt = 0; tt < 32; tt += 2) {
                int s0 = __shfl_sync(0xffffffffu, myidx, tt);
                int s1 = __shfl_sync(0xffffffffu, myidx, tt + 1);
                float2 v0 = __half22float2(fin[(size_t)s0 * 32 + lane]);
                float2 v1 = __half22float2(fin[(size_t)s1 * 32 + lane]);
                ax += v0.x; ay += v0.y;
                bx += v1.x; by += v1.y;
            }
        } else {
            for (int tt = 0; tt < rem; tt++) {
                int s0 = __shfl_sync(0xffffffffu, myidx, tt);
                float2 v0 = __half22float2(fin[(size_t)s0 * 32 + lane]);
                ax += v0.x; ay += v0.y;
            }
        }
    }
    return make_float2(ax + bx, ay + by);
}

// Step 1: g_feat2H[n] = half( norm[n]^2 * sum_{e in CSR[n]} g_featH[esrc[e]] )
__global__ __launch_bounds__(256) void k_gather1() {
    int node = (blockIdx.x * 256 + threadIdx.x) >> 5;
    if (node >= N_NODES) return;
    int lane = threadIdx.x & 31;
    float2 s = gather_sum(g_featH, node, lane);
    float nm = g_norm[node];
    float f = nm * nm;
    g_feat2H[(size_t)node * 32 + lane] = __floats2half2_rn(s.x * f, s.y * f);
}

// Step 2: out[n] = norm[n] * sum_{e in CSR[n]} g_feat2H[esrc[e]] + b  (fp32 out)
__global__ __launch_bounds__(256) void k_gather2(float* __restrict__ out,
                                                 const float* __restrict__ bias) {
    int node = (blockIdx.x * 256 + threadIdx.x) >> 5;
    if (node >= N_NODES) return;
    int lane = threadIdx.x & 31;
    float2 s = gather_sum(g_feat2H, node, lane);
    float nm = g_norm[node];
    float2 r;
    r.x = fmaf(s.x, nm, bias[2 * lane]);
    r.y = fmaf(s.y, nm, bias[2 * lane + 1]);
    ((float2*)out)[(size_t)node * 32 + lane] = r;
}

// ---------------------------------------------------------------------------
// Launch: inputs are x, src, dst, W, b (metadata order)
// ---------------------------------------------------------------------------
extern "C" void kernel_launch(void* const* d_in, const int* in_sizes, int n_in,
                              void* d_out, int out_size) {
    const float* x   = (const float*)d_in[0];
    const int*   src = (const int*)  d_in[1];
    const int*   dst = (const int*)  d_in[2];
    const float* W   = (const float*)d_in[3];
    const float* b   = (const float*)d_in[4];
    float*       out = (float*)d_out;

    k_zero<<<(N_NODES + 255) / 256, 256>>>();
    k_deg <<<(N_EDGES + 255) / 256, 256>>>(dst);
    k_scan<<<1, 1024>>>();
    k_csr <<<(N_EDGES + 255) / 256, 256>>>(src, dst);

    k_gemm<<<(N_NODES + MT - 1) / MT, 256>>>(x, W);

    int gather_blocks = (N_NODES * 32 + 255) / 256;   // warp per node
    k_gather1<<<gather_blocks, 256>>>();
    k_gather2<<<gather_blocks, 256>>>(out, b);
}